// round 9
// baseline (speedup 1.0000x reference)
#include <cuda_runtime.h>
#include <cstdint>

// Problem constants
#define B    16
#define H    512
#define W    512
#define KR   15                   // pad / half-window
#define INV_WIN2 (1.0f / 961.0f)

#define SEGS 32                   // row segments per image
#define ROWS 16                   // rows per block
#define RPB  4                    // rows per pipeline batch
#define NB   (ROWS / RPB)         // 4 batches
#define RD   64                   // ring depth; span y0-15..y0+31 = 47 rows
#define RW   18                   // 16 data words + 2 zero pads
#define NT   256                  // threads per block (2 columns each)
#define GRID (B * SEGS)           // 512

__device__ float4 g_part[GRID];   // per-block partial sums
__device__ int    g_done;         // zero-init; self-resets each run

// ---------------------------------------------------------------------------
// cp.async helpers (LDGSTS): 16B global->shared, deep pipeline, no registers.
// ---------------------------------------------------------------------------
__device__ __forceinline__ void cp16(void* dst_smem, const void* src_gmem)
{
    unsigned s = (unsigned)__cvta_generic_to_shared(dst_smem);
    asm volatile("cp.async.cg.shared.global [%0], [%1], 16;\n"
                 :: "r"(s), "l"(src_gmem));
}
__device__ __forceinline__ void cp_commit()
{
    asm volatile("cp.async.commit_group;\n");
}
template <int N>
__device__ __forceinline__ void cp_wait()
{
    asm volatile("cp.async.wait_group %0;\n" :: "n"(N));
}

// ---------------------------------------------------------------------------
// Build one 32-column row bitmask word in one thread (no shuffles).
// bit = (v == 1); {0,255} -> 0.
// ---------------------------------------------------------------------------
template <bool IS64>
__device__ __forceinline__ uint32_t load_word(const int* __restrict__ m,
                                              int bi, int yy, int wIdx)
{
    uint32_t word = 0;
    if (IS64) {
        const int4* p = (const int4*)m +
            ((size_t)bi * 131072 + (size_t)yy * 256 + wIdx * 16);
#pragma unroll
        for (int j = 0; j < 16; ++j) {          // 16 independent LDG.128
            int4 q = p[j];                      // two int64: lows at .x/.z
            word |= (((uint32_t)(q.x == 1)) |
                     ((uint32_t)(q.z == 1) << 1)) << (2 * j);
        }
    } else {
        const int4* p = (const int4*)m +
            ((size_t)bi * 65536 + (size_t)yy * 128 + wIdx * 8);
#pragma unroll
        for (int j = 0; j < 8; ++j) {           // 8 independent LDG.128
            int4 q = p[j];
            word |= (((uint32_t)(q.x == 1))      |
                     ((uint32_t)(q.y == 1) << 1) |
                     ((uint32_t)(q.z == 1) << 2) |
                     ((uint32_t)(q.w == 1) << 3)) << (4 * j);
        }
    }
    return word;
}

// 2-column horizontal 31-bit window popcounts sharing 3 padded-word loads.
// rw = padded ring row [pad, w0..w15, pad]; dw = data word of the column pair.
__device__ __forceinline__ void hcount2(const uint32_t* __restrict__ rw,
                                        int dw, const int* __restrict__ sel,
                                        const int* __restrict__ sh,
                                        int* __restrict__ out)
{
    const uint32_t p0 = rw[dw], p1 = rw[dw + 1], p2 = rw[dw + 2];
#pragma unroll
    for (int i = 0; i < 2; ++i) {
        uint32_t lo = sel[i] ? p1 : p0;
        uint32_t hi = sel[i] ? p2 : p1;
        out[i] = __popc(__funnelshift_r(lo, hi, sh[i]) & 0x7FFFFFFFu);
    }
}

// Per-pixel fused math.
__device__ __forceinline__ void pixel(float a0, float a1, int mi, float pooled,
                                      float& aw, float& awb, float& ai, float& ac)
{
    const float mf = (float)mi;
    const float wgt = 1.0f + 5.0f * fabsf(pooled - mf);

    // 2-class log-softmax, softplus form: d = a1-a0, e = exp(-|d|)
    const float d  = a1 - a0;
    const float e  = __expf(-fabsf(d));
    const float sp = __logf(1.0f + e);
    const float wb = sp + fmaxf(mi ? -d : d, 0.0f);   // -logp[target]
    const float rc = __frcp_rn(1.0f + e);
    const float sp1 = (d >= 0.0f) ? rc : e * rc;      // sigmoid(d) = p1

    aw  += wgt;
    awb += wgt * wb;
    ai  += sp1 * mf * wgt;
    ac  += (sp1 + mf) * wgt;
}

// ---------------------------------------------------------------------------
// Fused body. One block per (image, 16-row segment); thread t owns columns
// 2t, 2t+1 and all 16 rows. Pred streamed via double-buffered cp.async;
// mask via bitmask ring + sliding popcount window.
// ---------------------------------------------------------------------------
template <bool IS64>
__device__ __forceinline__ void fused_body(const float* __restrict__ pred,
                                           const int* __restrict__ mask,
                                           float* __restrict__ out)
{
    const int bi  = blockIdx.x >> 5;           // /SEGS
    const int seg = blockIdx.x & (SEGS - 1);
    const int y0  = seg * ROWS;
    const int t   = threadIdx.x;
    const int lane = t & 31;
    const int w    = t >> 5;

    const int dw = t >> 4;                     // data word of cols 2t,2t+1
    const int lq = (2 * t) & 31;               // even, 0..30
    int sel[2], sh[2];
#pragma unroll
    for (int i = 0; i < 2; ++i) {
        sel[i] = (lq + i) >= 15;
        sh[i]  = (lq + i + 17) & 31;
    }

    __shared__ uint32_t ring[RD][RW];
    __shared__ float    PB[2][RPB][2][W];      // [buf][row][ch][col] 32 KB

    // Zero pad words (row-invariant); covered by prologue sync.
    if (t < 2 * RD) ring[t >> 1][(t & 1) ? (RW - 1) : 0] = 0u;

    const float* pbase = pred + (size_t)bi * 524288;   // ch1 at +262144

    // Prologue: issue cp.async for pred batch 0 (rows y0..y0+3).
#pragma unroll
    for (int c = t; c < 1024; c += NT) {       // 1024 float4 chunks / stage
        const int row = c >> 8, ch = (c >> 7) & 1, c4 = c & 127;
        cp16(&PB[0][row][ch][c4 * 4],
             pbase + ch * 262144 + (size_t)(y0 + row) * 512 + c4 * 4);
    }
    cp_commit();

    // Ring warm-up: rows y0-15 .. y0+19 (35 rows x 16 words = 560 tasks).
    for (int task = t; task < 35 * 16; task += NT) {
        const int row = y0 - 15 + (task >> 4);
        const int wi  = task & 15;
        uint32_t word = (row >= 0 && row < H)
                      ? load_word<IS64>(mask, bi, row, wi) : 0u;
        ring[row & (RD - 1)][1 + wi] = word;
    }
    __syncthreads();

    // vsum init for row y0 (window rows y0-15..y0+15).
    int vs[2] = {0, 0};
#pragma unroll
    for (int k = -KR; k <= KR; ++k) {
        int hc[2];
        hcount2(ring[(y0 + k) & (RD - 1)], dw, sel, sh, hc);
        vs[0] += hc[0]; vs[1] += hc[1];
    }

    float aw = 0.0f, awb = 0.0f, ai = 0.0f, ac = 0.0f;

    for (int it = 0; it < NB; ++it) {
        // Issue next pred batch + next 4 ring rows, then drain current batch.
        if (it < NB - 1) {
            const int yb = y0 + (it + 1) * RPB;
#pragma unroll
            for (int c = t; c < 1024; c += NT) {
                const int row = c >> 8, ch = (c >> 7) & 1, c4 = c & 127;
                cp16(&PB[(it + 1) & 1][row][ch][c4 * 4],
                     pbase + ch * 262144 + (size_t)(yb + row) * 512 + c4 * 4);
            }
            cp_commit();
            // Ring lookahead rows y0+20+4it .. +3 (64 word-tasks).
            if (t < 64) {
                const int row = y0 + 20 + 4 * it + (t >> 4);
                const int wi  = t & 15;
                uint32_t word = (row < H) ? load_word<IS64>(mask, bi, row, wi) : 0u;
                ring[row & (RD - 1)][1 + wi] = word;
            }
            cp_wait<1>();      // batch `it` complete (one group still pending)
        } else {
            cp_wait<0>();      // final batch complete
        }
        __syncthreads();
        // Each ring slot is written exactly once per block (span 47 <= 64);
        // write(lookahead it) -> read(compute it+1) is ordered by the sync
        // of iteration it+1.

        // Compute 4 rows, 2 columns each, pred from smem.
        const int buf = it & 1;
#pragma unroll
        for (int r = 0; r < RPB; ++r) {
            const int y = y0 + it * RPB + r;

            const uint32_t cw = ring[y & (RD - 1)][1 + dw];
            const float2 a0 = *(const float2*)&PB[buf][r][0][2 * t];
            const float2 a1 = *(const float2*)&PB[buf][r][1][2 * t];

            pixel(a0.x, a1.x, (cw >> lq) & 1,
                  (float)vs[0] * INV_WIN2, aw, awb, ai, ac);
            pixel(a0.y, a1.y, (cw >> (lq + 1)) & 1,
                  (float)vs[1] * INV_WIN2, aw, awb, ai, ac);

            // slide vertical windows (exact integer arithmetic)
            int ha[2], hr[2];
            hcount2(ring[(y + KR + 1) & (RD - 1)], dw, sel, sh, ha);
            hcount2(ring[(y - KR) & (RD - 1)],     dw, sel, sh, hr);
            vs[0] += ha[0] - hr[0];
            vs[1] += ha[1] - hr[1];
        }
        __syncthreads();   // protect PB[buf] before it is re-issued next iter
    }

    // Deterministic reduction: warp butterfly + fixed-order combine.
#pragma unroll
    for (int o = 16; o > 0; o >>= 1) {
        aw  += __shfl_xor_sync(0xFFFFFFFFu, aw,  o);
        awb += __shfl_xor_sync(0xFFFFFFFFu, awb, o);
        ai  += __shfl_xor_sync(0xFFFFFFFFu, ai,  o);
        ac  += __shfl_xor_sync(0xFFFFFFFFu, ac,  o);
    }
    __shared__ float4 s4[NT / 32];
    __shared__ int amLast;
    if (lane == 0) s4[w] = make_float4(aw, awb, ai, ac);
    __syncthreads();
    if (t == 0) {
        float4 acc = s4[0];
#pragma unroll
        for (int i = 1; i < NT / 32; ++i) {
            float4 p = s4[i];
            acc.x += p.x; acc.y += p.y; acc.z += p.z; acc.w += p.w;
        }
        g_part[blockIdx.x] = acc;
        __threadfence();
        amLast = (atomicAdd(&g_done, 1) == GRID - 1);
    }
    __syncthreads();

    // Last block finalizes (deterministic: fixed-order reads of g_part).
    if (amLast) {
        __shared__ double sh2[B];
        if (t < B) {
            double taw = 0.0, tawb = 0.0, tai = 0.0, tac = 0.0;
            for (int s = 0; s < SEGS; ++s) {
                float4 p = g_part[t * SEGS + s];
                taw += p.x; tawb += p.y; tai += p.z; tac += p.w;
            }
            double wbce = tawb / taw;
            double uni  = tac - tai;
            double wiou = 1.0 - (tai + 1.0) / (uni + 1.0);
            sh2[t] = wbce + wiou;
        }
        __syncthreads();
        if (t == 0) {
            double z = 0.0;
#pragma unroll
            for (int i = 0; i < B; ++i) z += sh2[i];
            out[0] = (float)(z / (double)B);
            g_done = 0;   // reset for next (graph-replayed) execution
        }
    }
}

// ---------------------------------------------------------------------------
// Entry: in-kernel mask dtype probe (uniform across block). int64 LE high
// words are all zero; int32 random {0,1} data has a nonzero odd word within
// the first 512 ints with probability 1 - 2^-256.
// ---------------------------------------------------------------------------
__global__ void __launch_bounds__(NT)
fused_kernel(const float* __restrict__ pred, const int* __restrict__ mask,
             float* __restrict__ out)
{
    const unsigned o = ((const unsigned*)mask)[2 * threadIdx.x + 1];
    if (__syncthreads_or(o != 0u)) fused_body<false>(pred, mask, out);
    else                           fused_body<true >(pred, mask, out);
}

// ---------------------------------------------------------------------------
extern "C" void kernel_launch(void* const* d_in, const int* in_sizes, int n_in,
                              void* d_out, int out_size)
{
    // Identify inputs by element count (robust to metadata ordering):
    // pred = 16*2*512*512 = 8388608, mask = 16*512*512 = 4194304.
    int pi = 0, mi = 1;
    if (n_in >= 2 && in_sizes[0] == 4194304 && in_sizes[1] == 8388608) {
        pi = 1; mi = 0;
    }
    const float* pred = (const float*)d_in[pi];  // [16,2,512,512] fp32
    const int*   mask = (const int*)d_in[mi];    // [16,512,512] int32 OR int64
    float* out = (float*)d_out;

    fused_kernel<<<GRID, NT>>>(pred, mask, out);
}

// round 10
// speedup vs baseline: 1.1380x; 1.1380x over previous
#include <cuda_runtime.h>
#include <cstdint>

// Problem constants
#define B    16
#define H    512
#define W    512
#define KR   15                   // pad / half-window
#define INV_WIN2 (1.0f / 961.0f)

#define SEGS 32                   // row segments per image
#define ROWS 16                   // rows per block
#define RD   64                   // ring depth; span y0-15..y0+31 = 47 rows
#define RW   18                   // 16 data words + 2 zero pads
#define NT   256                  // threads per block (2 columns each)
#define GRID (B * SEGS)           // 512
#define NWORDS (B * H * (W / 32)) // 131072 bit-plane words

__device__ uint32_t g_bits[NWORDS];   // 512 KB mask bit-plane
__device__ float4   g_part[GRID];     // per-block partial sums
__device__ int      g_done;           // zero-init; self-resets each run

// ---------------------------------------------------------------------------
// Kernel A: pack mask into 1 bit/pixel. bit = (v == 1); {0,255} -> 0.
// One word (32 consecutive elements) per thread; pure streaming.
// ---------------------------------------------------------------------------
template <bool IS64>
__device__ __forceinline__ uint32_t pack_word(const int* __restrict__ m, int gw)
{
    uint32_t word = 0;
    if (IS64) {
        const int4* p = (const int4*)m + (size_t)gw * 16;
#pragma unroll
        for (int j = 0; j < 16; ++j) {            // 16 independent LDG.128
            int4 q = p[j];                        // two int64: lows at .x/.z
            word |= (((uint32_t)(q.x == 1)) |
                     ((uint32_t)(q.z == 1) << 1)) << (2 * j);
        }
    } else {
        const int4* p = (const int4*)m + (size_t)gw * 8;
#pragma unroll
        for (int j = 0; j < 8; ++j) {             // 8 independent LDG.128
            int4 q = p[j];
            word |= (((uint32_t)(q.x == 1))      |
                     ((uint32_t)(q.y == 1) << 1) |
                     ((uint32_t)(q.z == 1) << 2) |
                     ((uint32_t)(q.w == 1) << 3)) << (4 * j);
        }
    }
    return word;
}

// In-kernel dtype probe (uniform per block): int64 LE high words are all
// zero; int32 random {0,1} data has a nonzero odd int within the first 512
// ints with probability 1 - 2^-256.
__global__ void __launch_bounds__(NT)
bitpack_kernel(const int* __restrict__ mask)
{
    const int gw = blockIdx.x * NT + threadIdx.x;
    const unsigned o = ((const unsigned*)mask)[2 * threadIdx.x + 1];
    if (__syncthreads_or(o != 0u)) g_bits[gw] = pack_word<false>(mask, gw);
    else                           g_bits[gw] = pack_word<true >(mask, gw);
}

// ---------------------------------------------------------------------------
// 2-column horizontal 31-bit window popcounts sharing 3 padded-word loads.
// rw = padded ring row [pad, w0..w15, pad]; dw = (2t)>>5 (pre-correction).
// ---------------------------------------------------------------------------
__device__ __forceinline__ void hcount2(const uint32_t* __restrict__ rw,
                                        int dw, const int* __restrict__ sel,
                                        const int* __restrict__ sh,
                                        int* __restrict__ out)
{
    const uint32_t p0 = rw[dw], p1 = rw[dw + 1], p2 = rw[dw + 2];
#pragma unroll
    for (int i = 0; i < 2; ++i) {
        uint32_t lo = sel[i] ? p1 : p0;
        uint32_t hi = sel[i] ? p2 : p1;
        out[i] = __popc(__funnelshift_r(lo, hi, sh[i]) & 0x7FFFFFFFu);
    }
}

// Per-pixel fused math.
__device__ __forceinline__ void pixel(float a0, float a1, int mi, float pooled,
                                      float& aw, float& awb, float& ai, float& ac)
{
    const float mf = (float)mi;
    const float wgt = 1.0f + 5.0f * fabsf(pooled - mf);

    // 2-class log-softmax, softplus form: d = a1-a0, e = exp(-|d|)
    const float d  = a1 - a0;
    const float e  = __expf(-fabsf(d));
    const float sp = __logf(1.0f + e);
    const float wb = sp + fmaxf(mi ? -d : d, 0.0f);   // -logp[target]
    const float rc = __frcp_rn(1.0f + e);
    const float sp1 = (d >= 0.0f) ? rc : e * rc;      // sigmoid(d) = p1

    aw  += wgt;
    awb += wgt * wb;
    ai  += sp1 * mf * wgt;
    ac  += (sp1 + mf) * wgt;
}

// ---------------------------------------------------------------------------
// Kernel B. One block per (image, 16-row segment); thread t owns columns
// 2t, 2t+1 for all 16 rows. Ring words from g_bits; per-row horizontal
// popcounts cached once in smem as uchar; barrier-free 16-row compute.
// ---------------------------------------------------------------------------
__global__ void __launch_bounds__(NT, 3)
fused_kernel(const float* __restrict__ pred, float* __restrict__ out)
{
    const int bi  = blockIdx.x >> 5;           // /SEGS
    const int seg = blockIdx.x & (SEGS - 1);
    const int y0  = seg * ROWS;
    const int t   = threadIdx.x;
    const int lane = t & 31;
    const int w    = t >> 5;

    const int dw = t >> 4;                     // (2t)>>5
    const int lq = (2 * t) & 31;               // even, 0..30
    int sel[2], sh[2];
#pragma unroll
    for (int i = 0; i < 2; ++i) {
        sel[i] = (lq + i) >= 15;
        sh[i]  = (lq + i + 17) & 31;
    }

    __shared__ uint32_t ring[RD][RW];          // 4.6 KB bitmask rows (padded)
    __shared__ uint8_t  hsumS[RD][W];          // 32 KB per-row 31-popcounts

    // Zero pad words (row-invariant); covered by first sync.
    if (t < 2 * RD) ring[t >> 1][(t & 1) ? (RW - 1) : 0] = 0u;

    // Phase 1: ring-fill rows y0-15 .. y0+31 (47 rows) from the bit-plane.
    const uint32_t* bb = g_bits + bi * (H * 16);
    for (int task = t; task < 47 * 16; task += NT) {
        const int row = y0 - 15 + (task >> 4);
        const int wi  = task & 15;
        ring[row & (RD - 1)][1 + wi] =
            (row >= 0 && row < H) ? bb[row * 16 + wi] : 0u;
    }
    __syncthreads();

    // Phase 2: horizontal popcounts for all 47 rows, this thread's 2 cols.
#pragma unroll 1
    for (int k = 0; k < 47; ++k) {
        const int row = y0 - 15 + k;           // OOB rows: ring zeros -> hc 0
        int hc[2];
        hcount2(ring[row & (RD - 1)], dw, sel, sh, hc);
        *(uchar2*)&hsumS[row & (RD - 1)][2 * t] =
            make_uchar2((uint8_t)hc[0], (uint8_t)hc[1]);
    }
    __syncthreads();

    // vsum init for row y0 (window rows y0-15..y0+15).
    int vs0 = 0, vs1 = 0;
#pragma unroll
    for (int k = -KR; k <= KR; ++k) {
        uchar2 hv = *(const uchar2*)&hsumS[(y0 + k) & (RD - 1)][2 * t];
        vs0 += hv.x; vs1 += hv.y;
    }

    // Barrier-free compute: 16 rows, 2 columns each.
    const float* p0 = pred + (size_t)bi * 524288;      // ch0
    const float* p1 = p0 + 262144;                     // ch1
    float aw = 0.0f, awb = 0.0f, ai = 0.0f, ac = 0.0f;

#pragma unroll 4
    for (int r = 0; r < ROWS; ++r) {
        const int y = y0 + r;

        const uint32_t cw = ring[y & (RD - 1)][1 + dw];
        const float2 a0 = *(const float2*)(p0 + (size_t)y * 512 + 2 * t);
        const float2 a1 = *(const float2*)(p1 + (size_t)y * 512 + 2 * t);

        pixel(a0.x, a1.x, (cw >> lq) & 1,
              (float)vs0 * INV_WIN2, aw, awb, ai, ac);
        pixel(a0.y, a1.y, (cw >> (lq + 1)) & 1,
              (float)vs1 * INV_WIN2, aw, awb, ai, ac);

        // slide vertical windows: +row(y+16), -row(y-15); exact integers.
        uchar2 ha = *(const uchar2*)&hsumS[(y + KR + 1) & (RD - 1)][2 * t];
        uchar2 hr = *(const uchar2*)&hsumS[(y - KR) & (RD - 1)][2 * t];
        vs0 += (int)ha.x - (int)hr.x;
        vs1 += (int)ha.y - (int)hr.y;
    }

    // Deterministic reduction: warp butterfly + fixed-order combine.
#pragma unroll
    for (int o = 16; o > 0; o >>= 1) {
        aw  += __shfl_xor_sync(0xFFFFFFFFu, aw,  o);
        awb += __shfl_xor_sync(0xFFFFFFFFu, awb, o);
        ai  += __shfl_xor_sync(0xFFFFFFFFu, ai,  o);
        ac  += __shfl_xor_sync(0xFFFFFFFFu, ac,  o);
    }
    __shared__ float4 s4[NT / 32];
    __shared__ int amLast;
    if (lane == 0) s4[w] = make_float4(aw, awb, ai, ac);
    __syncthreads();
    if (t == 0) {
        float4 acc = s4[0];
#pragma unroll
        for (int i = 1; i < NT / 32; ++i) {
            float4 p = s4[i];
            acc.x += p.x; acc.y += p.y; acc.z += p.z; acc.w += p.w;
        }
        g_part[blockIdx.x] = acc;
        __threadfence();
        amLast = (atomicAdd(&g_done, 1) == GRID - 1);
    }
    __syncthreads();

    // Last block finalizes (deterministic: fixed-order reads of g_part).
    if (amLast) {
        __shared__ double sh2[B];
        if (t < B) {
            double taw = 0.0, tawb = 0.0, tai = 0.0, tac = 0.0;
            for (int s = 0; s < SEGS; ++s) {
                float4 p = g_part[t * SEGS + s];
                taw += p.x; tawb += p.y; tai += p.z; tac += p.w;
            }
            double wbce = tawb / taw;
            double uni  = tac - tai;
            double wiou = 1.0 - (tai + 1.0) / (uni + 1.0);
            sh2[t] = wbce + wiou;
        }
        __syncthreads();
        if (t == 0) {
            double z = 0.0;
#pragma unroll
            for (int i = 0; i < B; ++i) z += sh2[i];
            out[0] = (float)(z / (double)B);
            g_done = 0;   // reset for next (graph-replayed) execution
        }
    }
}

// ---------------------------------------------------------------------------
extern "C" void kernel_launch(void* const* d_in, const int* in_sizes, int n_in,
                              void* d_out, int out_size)
{
    // Identify inputs by element count (robust to metadata ordering):
    // pred = 16*2*512*512 = 8388608, mask = 16*512*512 = 4194304.
    int pi = 0, mi = 1;
    if (n_in >= 2 && in_sizes[0] == 4194304 && in_sizes[1] == 8388608) {
        pi = 1; mi = 0;
    }
    const float* pred = (const float*)d_in[pi];  // [16,2,512,512] fp32
    const int*   mask = (const int*)d_in[mi];    // [16,512,512] int32 OR int64
    float* out = (float*)d_out;

    bitpack_kernel<<<NWORDS / NT, NT>>>(mask);
    fused_kernel<<<GRID, NT>>>(pred, out);
}